// round 1
// baseline (speedup 1.0000x reference)
#include <cuda_runtime.h>
#include <cstdint>

// Problem constants
#define Bz   256
#define Tz   512
#define Ez   200
#define Hz   100
#define NCz  5
#define BT   131072      // B*T

// ---------------- scratch (static device allocations) ----------------
__device__ float g_scale[BT];
__device__ float g_xp[(size_t)BT * 300];   // 157 MB
__device__ float g_rnn[(size_t)BT * 100];  // 52 MB
__device__ float g_ti[(size_t)BT * 100];   // 52 MB
__device__ float g_z[BT];
__device__ float g_li[BT];
__device__ float g_state[Bz * Hz];

// ---------------- helpers ----------------
__device__ __forceinline__ float sigf(float x) {
    return 1.0f / (1.0f + __expf(-x));
}
__device__ __forceinline__ float tanh_fast(float x) {
    float t = __expf(-2.0f * fabsf(x));      // in (0,1], no overflow
    float r = (1.0f - t) / (1.0f + t);
    return copysignf(r, x);
}
__device__ __forceinline__ float to_tf32(float x) {
    uint32_t u;
    asm("cvt.rna.tf32.f32 %0, %1;" : "=r"(u) : "f"(x));
    return __uint_as_float(u);
}

// ---------------- K1: per-row embedding norm scale ----------------
__global__ void __launch_bounds__(256) scale_kernel(const int* __restrict__ txt,
                                                    const float* __restrict__ emb) {
    int warp = (blockIdx.x * 256 + threadIdx.x) >> 5;
    int lane = threadIdx.x & 31;
    if (warp >= BT) return;
    int tok = txt[warp];
    const float* row = emb + (size_t)tok * Ez;
    float ss = 0.f;
    for (int k = lane; k < Ez; k += 32) { float v = row[k]; ss += v * v; }
    #pragma unroll
    for (int o = 16; o > 0; o >>= 1) ss += __shfl_xor_sync(0xffffffffu, ss, o);
    if (lane == 0) {
        float n = sqrtf(ss);
        g_scale[warp] = (n > 1.0f) ? 1.0f / (n + 1e-7f) : 1.0f;
    }
}

// ---------------- tf32 MMA GEMM: C[M,NV] = A[M,K] @ W[NV,K]^T + bias ----------------
// TM=64 rows/block, TN cols/block, 8 warps = 2(m) x 4(n). m16n8k8 tf32.
template <int KDIM, int KCEIL, int KSTR, int TN, int WNc, bool GATHER>
__global__ void __launch_bounds__(256) mma_gemm_kernel(
    const float* __restrict__ Ain,    // used if !GATHER: [M,KDIM]
    const int* __restrict__ txt,      // used if GATHER
    const float* __restrict__ emb,    // used if GATHER
    const float* __restrict__ W,      // [NV, KDIM]
    const float* __restrict__ bias,   // [NV]
    float* __restrict__ C,            // [M, NV]
    int NV)
{
    extern __shared__ float sm[];
    float* As = sm;                   // 64 * KSTR
    float* Bs = sm + 64 * KSTR;       // TN * KSTR
    __shared__ int   s_tok[64];
    __shared__ float s_scl[64];

    const int tid   = threadIdx.x;
    const int rbase = blockIdx.x * 64;
    const int nbase = blockIdx.y * TN;

    if (GATHER) {
        if (tid < 64) {
            int r = rbase + tid;
            s_tok[tid] = txt[r];
            s_scl[tid] = g_scale[r];
        }
        __syncthreads();
    }

    const int K4 = KCEIL / 4;
    // fill A (tf32-converted)
    for (int e = tid; e < 64 * K4; e += 256) {
        int row = e / K4, k4 = e % K4;
        float4 v = make_float4(0.f, 0.f, 0.f, 0.f);
        if (4 * k4 + 3 < KDIM) {
            if (GATHER) {
                const float4* p = (const float4*)(emb + (size_t)s_tok[row] * KDIM) + k4;
                v = *p;
                float s = s_scl[row];
                v.x *= s; v.y *= s; v.z *= s; v.w *= s;
            } else {
                const float4* p = (const float4*)(Ain + (size_t)(rbase + row) * KDIM) + k4;
                v = *p;
            }
        }
        float4 o = make_float4(to_tf32(v.x), to_tf32(v.y), to_tf32(v.z), to_tf32(v.w));
        *(float4*)(As + row * KSTR + 4 * k4) = o;
    }
    // fill B
    for (int e = tid; e < TN * K4; e += 256) {
        int n = e / K4, k4 = e % K4;
        int ng = nbase + n;
        float4 v = make_float4(0.f, 0.f, 0.f, 0.f);
        if (ng < NV && 4 * k4 + 3 < KDIM) {
            const float4* p = (const float4*)(W + (size_t)ng * KDIM) + k4;
            v = *p;
        }
        float4 o = make_float4(to_tf32(v.x), to_tf32(v.y), to_tf32(v.z), to_tf32(v.w));
        *(float4*)(Bs + n * KSTR + 4 * k4) = o;
    }
    __syncthreads();

    const int wid  = tid >> 5;
    const int lane = tid & 31;
    const int g    = lane >> 2;
    const int tg   = lane & 3;
    const int mwarp = wid & 1;    // 0..1
    const int nwarp = wid >> 1;   // 0..3
    const int NF = WNc / 8;

    float c[2][NF][4];
    #pragma unroll
    for (int mt = 0; mt < 2; mt++)
        #pragma unroll
        for (int nf = 0; nf < NF; nf++)
            #pragma unroll
            for (int i = 0; i < 4; i++) c[mt][nf][i] = 0.f;

    const float* Aw = As + (mwarp * 32) * KSTR;
    const float* Bw = Bs + (nwarp * WNc) * KSTR;

    #pragma unroll 1
    for (int k8 = 0; k8 < KCEIL / 8; k8++) {
        int k0 = k8 * 8;
        uint32_t a[2][4], b[NF][2];
        #pragma unroll
        for (int mt = 0; mt < 2; mt++) {
            const float* ap = Aw + (mt * 16 + g) * KSTR + k0 + tg;
            a[mt][0] = __float_as_uint(ap[0]);
            a[mt][1] = __float_as_uint(ap[8 * KSTR]);
            a[mt][2] = __float_as_uint(ap[4]);
            a[mt][3] = __float_as_uint(ap[8 * KSTR + 4]);
        }
        #pragma unroll
        for (int nf = 0; nf < NF; nf++) {
            const float* bp = Bw + (nf * 8 + g) * KSTR + k0 + tg;
            b[nf][0] = __float_as_uint(bp[0]);
            b[nf][1] = __float_as_uint(bp[4]);
        }
        #pragma unroll
        for (int mt = 0; mt < 2; mt++)
            #pragma unroll
            for (int nf = 0; nf < NF; nf++) {
                asm volatile(
                    "mma.sync.aligned.m16n8k8.row.col.f32.tf32.tf32.f32 "
                    "{%0,%1,%2,%3}, {%4,%5,%6,%7}, {%8,%9}, {%0,%1,%2,%3};"
                    : "+f"(c[mt][nf][0]), "+f"(c[mt][nf][1]),
                      "+f"(c[mt][nf][2]), "+f"(c[mt][nf][3])
                    : "r"(a[mt][0]), "r"(a[mt][1]), "r"(a[mt][2]), "r"(a[mt][3]),
                      "r"(b[nf][0]), "r"(b[nf][1]));
            }
    }

    // store C (+bias)
    #pragma unroll
    for (int mt = 0; mt < 2; mt++) {
        int row = rbase + mwarp * 32 + mt * 16 + g;
        #pragma unroll
        for (int nf = 0; nf < NF; nf++) {
            int col = nbase + nwarp * WNc + nf * 8 + 2 * tg;
            if (col < NV) {
                float b0 = bias[col], b1 = bias[col + 1];
                float2 v0 = make_float2(c[mt][nf][0] + b0, c[mt][nf][1] + b1);
                float2 v1 = make_float2(c[mt][nf][2] + b0, c[mt][nf][3] + b1);
                *(float2*)(C + (size_t)row * NV + col) = v0;
                *(float2*)(C + (size_t)(row + 8) * NV + col) = v1;
            }
        }
    }
}

// ---------------- K3: GRU scan, 2 batch elements per block ----------------
__global__ void __launch_bounds__(320, 1) gru_kernel(const float* __restrict__ Whh,
                                                     const float* __restrict__ bhh) {
    __shared__ float2 h2[Hz];
    __shared__ float2 hp2[3 * Hz];
    const int tid = threadIdx.x;
    const int b0 = blockIdx.x * 2, b1 = b0 + 1;

    float w[Hz];
    float bh = 0.f;
    if (tid < 300) {
        #pragma unroll
        for (int k = 0; k < Hz; k++) w[k] = Whh[tid * Hz + k];
        bh = bhh[tid];
    }
    if (tid < Hz) h2[tid] = make_float2(0.f, 0.f);

    const float* x0 = g_xp + (size_t)b0 * Tz * 300;
    const float* x1 = g_xp + (size_t)b1 * Tz * 300;
    float2 xr, xz, xn;
    if (tid < Hz) {
        xr = make_float2(x0[tid],       x1[tid]);
        xz = make_float2(x0[Hz + tid],  x1[Hz + tid]);
        xn = make_float2(x0[200 + tid], x1[200 + tid]);
    }
    __syncthreads();

    for (int t = 0; t < Tz; t++) {
        float2 xrn, xzn, xnn;
        if (tid < Hz && t + 1 < Tz) {
            const float* p0 = x0 + (size_t)(t + 1) * 300 + tid;
            const float* p1 = x1 + (size_t)(t + 1) * 300 + tid;
            xrn = make_float2(p0[0],   p1[0]);
            xzn = make_float2(p0[Hz],  p1[Hz]);
            xnn = make_float2(p0[200], p1[200]);
        }
        if (tid < 300) {
            float ax = bh, ay = bh;
            #pragma unroll
            for (int k = 0; k < Hz; k++) {
                float2 h = h2[k];
                ax += w[k] * h.x;
                ay += w[k] * h.y;
            }
            hp2[tid] = make_float2(ax, ay);
        }
        __syncthreads();
        if (tid < Hz) {
            float2 hr = hp2[tid], hzv = hp2[Hz + tid], hn = hp2[200 + tid];
            float2 hold = h2[tid];
            float rx = sigf(xr.x + hr.x),  ry = sigf(xr.y + hr.y);
            float zx = sigf(xz.x + hzv.x), zy = sigf(xz.y + hzv.y);
            float nx = tanh_fast(xn.x + rx * hn.x);
            float ny = tanh_fast(xn.y + ry * hn.y);
            float hx = (1.f - zx) * nx + zx * hold.x;
            float hy = (1.f - zy) * ny + zy * hold.y;
            h2[tid] = make_float2(hx, hy);
            g_rnn[((size_t)b0 * Tz + t) * Hz + tid] = hx;
            g_rnn[((size_t)b1 * Tz + t) * Hz + tid] = hy;
            xr = xrn; xz = xzn; xn = xnn;
        }
        __syncthreads();
    }
}

// ---------------- K4: per-(b,t) z (attention gate) and lgr_in ----------------
__global__ void __launch_bounds__(256) zli_kernel(const float* __restrict__ Wlgr,
                                                  const int* __restrict__ lens) {
    int warp = (blockIdx.x * 256 + threadIdx.x) >> 5;
    int lane = threadIdx.x & 31;
    if (warp >= BT) return;
    int b = warp >> 9;          // /Tz
    int t = warp & (Tz - 1);
    const float* r = g_rnn + (size_t)warp * Hz;
    float s1 = 0.f, s2 = 0.f, s3 = 0.f;
    for (int k = lane; k < Hz; k += 32) {
        float v = r[k];
        s1 += v;
        s2 += v * v;
        s3 += v * Wlgr[k];      // W_lgr[:, :H]
    }
    #pragma unroll
    for (int o = 16; o > 0; o >>= 1) {
        s1 += __shfl_xor_sync(0xffffffffu, s1, o);
        s2 += __shfl_xor_sync(0xffffffffu, s2, o);
        s3 += __shfl_xor_sync(0xffffffffu, s3, o);
    }
    if (lane == 0) {
        float nrm = sqrtf(s2);
        float att = 0.001f * s1 / fmaxf(nrm, 1e-12f);   // qn = 0.1 each, /H
        float zv = (t < lens[b] && att > 0.f) ? att : 0.f;
        g_z[warp]  = zv;
        g_li[warp] = s3;
    }
}

// ---------------- K6: second recurrence, 2 batch elements per block ----------------
__global__ void __launch_bounds__(128, 1) rec_kernel(const float* __restrict__ Wts,
                                                     const float* __restrict__ bts,
                                                     const float* __restrict__ Wlgr,
                                                     const float* __restrict__ blgr) {
    __shared__ float2 st[Hz];
    __shared__ float2 pg[Hz];
    __shared__ float2 gsh;
    __shared__ float  aux[4];   // li0, li1, z0, z1
    const int tid = threadIdx.x;
    const int b0 = blockIdx.x * 2, b1 = b0 + 1;

    float w[Hz];
    float wl = 0.f, bt = 0.f;
    if (tid < Hz) {
        #pragma unroll
        for (int k = 0; k < Hz; k++) w[k] = Wts[tid * Hz + k];
        wl = Wlgr[Hz + tid];    // W_lgr[:, H:]
        bt = bts[tid];
        st[tid] = make_float2(0.f, 0.f);
    }
    const float bl = blgr[0];
    const float* t0 = g_ti + (size_t)b0 * Tz * Hz;
    const float* t1 = g_ti + (size_t)b1 * Tz * Hz;
    float2 tv = make_float2(0.f, 0.f);
    if (tid < Hz) tv = make_float2(t0[tid], t1[tid]);
    __syncthreads();

    for (int t = 0; t < Tz; t++) {
        float2 tn = make_float2(0.f, 0.f);
        float2 m2 = make_float2(0.f, 0.f);
        if (tid < Hz) {
            if (t + 1 < Tz)
                tn = make_float2(t0[(size_t)(t + 1) * Hz + tid],
                                 t1[(size_t)(t + 1) * Hz + tid]);
            #pragma unroll
            for (int k = 0; k < Hz; k++) {
                float2 s = st[k];
                m2.x += w[k] * s.x;
                m2.y += w[k] * s.y;
            }
            float2 s = st[tid];
            pg[tid] = make_float2(wl * s.x, wl * s.y);
        } else if (tid < 104) {
            int which = tid - Hz;   // 0..3
            if (which == 0) aux[0] = g_li[(size_t)b0 * Tz + t];
            if (which == 1) aux[1] = g_li[(size_t)b1 * Tz + t];
            if (which == 2) aux[2] = g_z[(size_t)b0 * Tz + t];
            if (which == 3) aux[3] = g_z[(size_t)b1 * Tz + t];
        }
        __syncthreads();
        if (tid < 32) {
            float ax = 0.f, ay = 0.f;
            for (int k = tid; k < Hz; k += 32) {
                ax += pg[k].x;
                ay += pg[k].y;
            }
            #pragma unroll
            for (int o = 16; o > 0; o >>= 1) {
                ax += __shfl_xor_sync(0xffffffffu, ax, o);
                ay += __shfl_xor_sync(0xffffffffu, ay, o);
            }
            if (tid == 0)
                gsh = make_float2(sigf(aux[0] + ax + bl), sigf(aux[1] + ay + bl));
        }
        __syncthreads();
        if (tid < Hz) {
            float2 gv = gsh;
            float nsx = tanh_fast(tv.x + gv.x * m2.x + bt);
            float nsy = tanh_fast(tv.y + gv.y * m2.y + bt);
            float zx = aux[2], zy = aux[3];
            float2 s = st[tid];
            st[tid] = make_float2((1.f - zx) * s.x + zx * nsx,
                                  (1.f - zy) * s.y + zy * nsy);
            tv = tn;
        }
        __syncthreads();
    }
    if (tid < Hz) {
        g_state[b0 * Hz + tid] = st[tid].x;
        g_state[b1 * Hz + tid] = st[tid].y;
    }
}

// ---------------- K7: output projection ----------------
__global__ void __launch_bounds__(256) out_kernel(const float* __restrict__ Wout,
                                                  const float* __restrict__ bout,
                                                  float* __restrict__ out) {
    int idx = blockIdx.x * 256 + threadIdx.x;
    if (idx >= Bz * NCz) return;
    int b = idx / NCz, c = idx % NCz;
    float acc = bout[c];
    const float* s = g_state + b * Hz;
    const float* wr = Wout + c * Hz;
    #pragma unroll
    for (int k = 0; k < Hz; k++) acc += s[k] * wr[k];
    out[idx] = acc;
}

// ---------------- launch ----------------
extern "C" void kernel_launch(void* const* d_in, const int* in_sizes, int n_in,
                              void* d_out, int out_size) {
    const int*   txt   = (const int*)d_in[0];
    const int*   lens  = (const int*)d_in[1];
    const float* emb   = (const float*)d_in[2];
    const float* W_ih  = (const float*)d_in[3];
    const float* W_hh  = (const float*)d_in[4];
    const float* b_ih  = (const float*)d_in[5];
    const float* b_hh  = (const float*)d_in[6];
    const float* W_lgr = (const float*)d_in[7];
    const float* b_lgr = (const float*)d_in[8];
    const float* W_ts  = (const float*)d_in[9];
    const float* b_ts  = (const float*)d_in[10];
    const float* W_ti  = (const float*)d_in[11];
    const float* b_ti  = (const float*)d_in[12];
    const float* W_out = (const float*)d_in[13];
    const float* b_out = (const float*)d_in[14];
    float* out = (float*)d_out;

    float* xp  = nullptr; cudaGetSymbolAddress((void**)&xp,  g_xp);
    float* rnn = nullptr; cudaGetSymbolAddress((void**)&rnn, g_rnn);
    float* ti  = nullptr; cudaGetSymbolAddress((void**)&ti,  g_ti);

    // K1: embedding-row norm scales
    scale_kernel<<<BT / 8, 256>>>(txt, emb);

    // K2: xp = norm(emb[txt]) @ W_ih^T + b_ih   (tf32 MMA)
    {
        constexpr int SMEM = (64 + 160) * 204 * 4;   // 182784 B
        cudaFuncSetAttribute((const void*)mma_gemm_kernel<200, 200, 204, 160, 40, true>,
                             cudaFuncAttributeMaxDynamicSharedMemorySize, SMEM);
        dim3 grid(BT / 64, 2);
        mma_gemm_kernel<200, 200, 204, 160, 40, true><<<grid, 256, SMEM>>>(
            nullptr, txt, emb, W_ih, b_ih, xp, 300);
    }

    // K3: GRU scan
    gru_kernel<<<Bz / 2, 320>>>(W_hh, b_hh);

    // K4: z (attention gate) and lgr_in
    zli_kernel<<<BT / 8, 256>>>(W_lgr, lens);

    // K5: ti = rnn @ W_ti^T + b_ti   (tf32 MMA)
    {
        constexpr int SMEM = (64 + 128) * 108 * 4;   // 82944 B
        cudaFuncSetAttribute((const void*)mma_gemm_kernel<100, 104, 108, 128, 32, false>,
                             cudaFuncAttributeMaxDynamicSharedMemorySize, SMEM);
        dim3 grid(BT / 64, 1);
        mma_gemm_kernel<100, 104, 108, 128, 32, false><<<grid, 256, SMEM>>>(
            rnn, nullptr, nullptr, W_ti, b_ti, ti, 100);
    }

    // K6: second recurrence
    rec_kernel<<<Bz / 2, 128>>>(W_ts, b_ts, W_lgr, b_lgr);

    // K7: output projection
    out_kernel<<<(Bz * NCz + 255) / 256, 256>>>(W_out, b_out, out);
}

// round 2
// speedup vs baseline: 1.0009x; 1.0009x over previous
#include <cuda_runtime.h>
#include <cstdint>

// Problem constants
#define Bz   256
#define Tz   512
#define Ez   200
#define Hz   100
#define NCz  5
#define BT   131072      // B*T

// ---------------- scratch (static device allocations) ----------------
__device__ float g_scale[BT];
__device__ float g_xp[(size_t)BT * 300];   // 157 MB
__device__ float g_rnn[(size_t)BT * 100];  // 52 MB
__device__ float g_ti[(size_t)BT * 100];   // 52 MB
__device__ float g_z[BT];
__device__ float g_li[BT];
__device__ float g_state[Bz * Hz];

// ---------------- helpers ----------------
__device__ __forceinline__ float sigf(float x) {
    return 1.0f / (1.0f + __expf(-x));
}
__device__ __forceinline__ float tanh_fast(float x) {
    float t = __expf(-2.0f * fabsf(x));      // in (0,1], no overflow
    float r = (1.0f - t) / (1.0f + t);
    return copysignf(r, x);
}
__device__ __forceinline__ float to_tf32(float x) {
    uint32_t u;
    asm("cvt.rna.tf32.f32 %0, %1;" : "=r"(u) : "f"(x));
    return __uint_as_float(u);
}

// ---------------- K1: per-row embedding norm scale ----------------
__global__ void __launch_bounds__(256) scale_kernel(const int* __restrict__ txt,
                                                    const float* __restrict__ emb) {
    int warp = (blockIdx.x * 256 + threadIdx.x) >> 5;
    int lane = threadIdx.x & 31;
    if (warp >= BT) return;
    int tok = txt[warp];
    const float* row = emb + (size_t)tok * Ez;
    float ss = 0.f;
    for (int k = lane; k < Ez; k += 32) { float v = row[k]; ss += v * v; }
    #pragma unroll
    for (int o = 16; o > 0; o >>= 1) ss += __shfl_xor_sync(0xffffffffu, ss, o);
    if (lane == 0) {
        float n = sqrtf(ss);
        g_scale[warp] = (n > 1.0f) ? 1.0f / (n + 1e-7f) : 1.0f;
    }
}

// ---------------- tf32 MMA GEMM: C[M,NV] = A[M,K] @ W[NV,K]^T + bias ----------------
// TM=64 rows/block, TN cols/block, 8 warps = 2(m) x 4(n). m16n8k8 tf32.
template <int KDIM, int KCEIL, int KSTR, int TN, int WNc, bool GATHER>
__global__ void __launch_bounds__(256) mma_gemm_kernel(
    const float* __restrict__ Ain,    // used if !GATHER: [M,KDIM]
    const int* __restrict__ txt,      // used if GATHER
    const float* __restrict__ emb,    // used if GATHER
    const float* __restrict__ W,      // [NV, KDIM]
    const float* __restrict__ bias,   // [NV]
    float* __restrict__ C,            // [M, NV]
    int NV)
{
    extern __shared__ float sm[];
    float* As = sm;                   // 64 * KSTR
    float* Bs = sm + 64 * KSTR;       // TN * KSTR
    __shared__ int   s_tok[64];
    __shared__ float s_scl[64];

    const int tid   = threadIdx.x;
    const int rbase = blockIdx.x * 64;
    const int nbase = blockIdx.y * TN;

    if (GATHER) {
        if (tid < 64) {
            int r = rbase + tid;
            s_tok[tid] = txt[r];
            s_scl[tid] = g_scale[r];
        }
        __syncthreads();
    }

    const int K4 = KCEIL / 4;
    // fill A (tf32-converted)
    for (int e = tid; e < 64 * K4; e += 256) {
        int row = e / K4, k4 = e % K4;
        float4 v = make_float4(0.f, 0.f, 0.f, 0.f);
        if (4 * k4 + 3 < KDIM) {
            if (GATHER) {
                const float4* p = (const float4*)(emb + (size_t)s_tok[row] * KDIM) + k4;
                v = *p;
                float s = s_scl[row];
                v.x *= s; v.y *= s; v.z *= s; v.w *= s;
            } else {
                const float4* p = (const float4*)(Ain + (size_t)(rbase + row) * KDIM) + k4;
                v = *p;
            }
        }
        float4 o = make_float4(to_tf32(v.x), to_tf32(v.y), to_tf32(v.z), to_tf32(v.w));
        *(float4*)(As + row * KSTR + 4 * k4) = o;
    }
    // fill B
    for (int e = tid; e < TN * K4; e += 256) {
        int n = e / K4, k4 = e % K4;
        int ng = nbase + n;
        float4 v = make_float4(0.f, 0.f, 0.f, 0.f);
        if (ng < NV && 4 * k4 + 3 < KDIM) {
            const float4* p = (const float4*)(W + (size_t)ng * KDIM) + k4;
            v = *p;
        }
        float4 o = make_float4(to_tf32(v.x), to_tf32(v.y), to_tf32(v.z), to_tf32(v.w));
        *(float4*)(Bs + n * KSTR + 4 * k4) = o;
    }
    __syncthreads();

    const int wid  = tid >> 5;
    const int lane = tid & 31;
    const int g    = lane >> 2;
    const int tg   = lane & 3;
    const int mwarp = wid & 1;    // 0..1
    const int nwarp = wid >> 1;   // 0..3
    const int NF = WNc / 8;

    float c[2][NF][4];
    #pragma unroll
    for (int mt = 0; mt < 2; mt++)
        #pragma unroll
        for (int nf = 0; nf < NF; nf++)
            #pragma unroll
            for (int i = 0; i < 4; i++) c[mt][nf][i] = 0.f;

    const float* Aw = As + (mwarp * 32) * KSTR;
    const float* Bw = Bs + (nwarp * WNc) * KSTR;

    #pragma unroll 1
    for (int k8 = 0; k8 < KCEIL / 8; k8++) {
        int k0 = k8 * 8;
        uint32_t a[2][4], b[NF][2];
        #pragma unroll
        for (int mt = 0; mt < 2; mt++) {
            const float* ap = Aw + (mt * 16 + g) * KSTR + k0 + tg;
            a[mt][0] = __float_as_uint(ap[0]);
            a[mt][1] = __float_as_uint(ap[8 * KSTR]);
            a[mt][2] = __float_as_uint(ap[4]);
            a[mt][3] = __float_as_uint(ap[8 * KSTR + 4]);
        }
        #pragma unroll
        for (int nf = 0; nf < NF; nf++) {
            const float* bp = Bw + (nf * 8 + g) * KSTR + k0 + tg;
            b[nf][0] = __float_as_uint(bp[0]);
            b[nf][1] = __float_as_uint(bp[4]);
        }
        #pragma unroll
        for (int mt = 0; mt < 2; mt++)
            #pragma unroll
            for (int nf = 0; nf < NF; nf++) {
                asm volatile(
                    "mma.sync.aligned.m16n8k8.row.col.f32.tf32.tf32.f32 "
                    "{%0,%1,%2,%3}, {%4,%5,%6,%7}, {%8,%9}, {%0,%1,%2,%3};"
                    : "+f"(c[mt][nf][0]), "+f"(c[mt][nf][1]),
                      "+f"(c[mt][nf][2]), "+f"(c[mt][nf][3])
                    : "r"(a[mt][0]), "r"(a[mt][1]), "r"(a[mt][2]), "r"(a[mt][3]),
                      "r"(b[nf][0]), "r"(b[nf][1]));
            }
    }

    // store C (+bias)
    #pragma unroll
    for (int mt = 0; mt < 2; mt++) {
        int row = rbase + mwarp * 32 + mt * 16 + g;
        #pragma unroll
        for (int nf = 0; nf < NF; nf++) {
            int col = nbase + nwarp * WNc + nf * 8 + 2 * tg;
            if (col < NV) {
                float b0 = bias[col], b1 = bias[col + 1];
                float2 v0 = make_float2(c[mt][nf][0] + b0, c[mt][nf][1] + b1);
                float2 v1 = make_float2(c[mt][nf][2] + b0, c[mt][nf][3] + b1);
                *(float2*)(C + (size_t)row * NV + col) = v0;
                *(float2*)(C + (size_t)(row + 8) * NV + col) = v1;
            }
        }
    }
}

// ---------------- K3: GRU scan, 2 batch elements per block ----------------
__global__ void __launch_bounds__(320, 1) gru_kernel(const float* __restrict__ Whh,
                                                     const float* __restrict__ bhh) {
    __shared__ float2 h2[Hz];
    __shared__ float2 hp2[3 * Hz];
    const int tid = threadIdx.x;
    const int b0 = blockIdx.x * 2, b1 = b0 + 1;

    float w[Hz];
    float bh = 0.f;
    if (tid < 300) {
        #pragma unroll
        for (int k = 0; k < Hz; k++) w[k] = Whh[tid * Hz + k];
        bh = bhh[tid];
    }
    if (tid < Hz) h2[tid] = make_float2(0.f, 0.f);

    const float* x0 = g_xp + (size_t)b0 * Tz * 300;
    const float* x1 = g_xp + (size_t)b1 * Tz * 300;
    float2 xr, xz, xn;
    if (tid < Hz) {
        xr = make_float2(x0[tid],       x1[tid]);
        xz = make_float2(x0[Hz + tid],  x1[Hz + tid]);
        xn = make_float2(x0[200 + tid], x1[200 + tid]);
    }
    __syncthreads();

    for (int t = 0; t < Tz; t++) {
        float2 xrn, xzn, xnn;
        if (tid < Hz && t + 1 < Tz) {
            const float* p0 = x0 + (size_t)(t + 1) * 300 + tid;
            const float* p1 = x1 + (size_t)(t + 1) * 300 + tid;
            xrn = make_float2(p0[0],   p1[0]);
            xzn = make_float2(p0[Hz],  p1[Hz]);
            xnn = make_float2(p0[200], p1[200]);
        }
        if (tid < 300) {
            float ax = bh, ay = bh;
            #pragma unroll
            for (int k = 0; k < Hz; k++) {
                float2 h = h2[k];
                ax += w[k] * h.x;
                ay += w[k] * h.y;
            }
            hp2[tid] = make_float2(ax, ay);
        }
        __syncthreads();
        if (tid < Hz) {
            float2 hr = hp2[tid], hzv = hp2[Hz + tid], hn = hp2[200 + tid];
            float2 hold = h2[tid];
            float rx = sigf(xr.x + hr.x),  ry = sigf(xr.y + hr.y);
            float zx = sigf(xz.x + hzv.x), zy = sigf(xz.y + hzv.y);
            float nx = tanh_fast(xn.x + rx * hn.x);
            float ny = tanh_fast(xn.y + ry * hn.y);
            float hx = (1.f - zx) * nx + zx * hold.x;
            float hy = (1.f - zy) * ny + zy * hold.y;
            h2[tid] = make_float2(hx, hy);
            g_rnn[((size_t)b0 * Tz + t) * Hz + tid] = hx;
            g_rnn[((size_t)b1 * Tz + t) * Hz + tid] = hy;
            xr = xrn; xz = xzn; xn = xnn;
        }
        __syncthreads();
    }
}

// ---------------- K4: per-(b,t) z (attention gate) and lgr_in ----------------
__global__ void __launch_bounds__(256) zli_kernel(const float* __restrict__ Wlgr,
                                                  const int* __restrict__ lens) {
    int warp = (blockIdx.x * 256 + threadIdx.x) >> 5;
    int lane = threadIdx.x & 31;
    if (warp >= BT) return;
    int b = warp >> 9;          // /Tz
    int t = warp & (Tz - 1);
    const float* r = g_rnn + (size_t)warp * Hz;
    float s1 = 0.f, s2 = 0.f, s3 = 0.f;
    for (int k = lane; k < Hz; k += 32) {
        float v = r[k];
        s1 += v;
        s2 += v * v;
        s3 += v * Wlgr[k];      // W_lgr[:, :H]
    }
    #pragma unroll
    for (int o = 16; o > 0; o >>= 1) {
        s1 += __shfl_xor_sync(0xffffffffu, s1, o);
        s2 += __shfl_xor_sync(0xffffffffu, s2, o);
        s3 += __shfl_xor_sync(0xffffffffu, s3, o);
    }
    if (lane == 0) {
        float nrm = sqrtf(s2);
        float att = 0.001f * s1 / fmaxf(nrm, 1e-12f);   // qn = 0.1 each, /H
        float zv = (t < lens[b] && att > 0.f) ? att : 0.f;
        g_z[warp]  = zv;
        g_li[warp] = s3;
    }
}

// ---------------- K6: second recurrence, 2 batch elements per block ----------------
__global__ void __launch_bounds__(128, 1) rec_kernel(const float* __restrict__ Wts,
                                                     const float* __restrict__ bts,
                                                     const float* __restrict__ Wlgr,
                                                     const float* __restrict__ blgr) {
    __shared__ float2 st[Hz];
    __shared__ float2 pg[Hz];
    __shared__ float2 gsh;
    __shared__ float  aux[4];   // li0, li1, z0, z1
    const int tid = threadIdx.x;
    const int b0 = blockIdx.x * 2, b1 = b0 + 1;

    float w[Hz];
    float wl = 0.f, bt = 0.f;
    if (tid < Hz) {
        #pragma unroll
        for (int k = 0; k < Hz; k++) w[k] = Wts[tid * Hz + k];
        wl = Wlgr[Hz + tid];    // W_lgr[:, H:]
        bt = bts[tid];
        st[tid] = make_float2(0.f, 0.f);
    }
    const float bl = blgr[0];
    const float* t0 = g_ti + (size_t)b0 * Tz * Hz;
    const float* t1 = g_ti + (size_t)b1 * Tz * Hz;
    float2 tv = make_float2(0.f, 0.f);
    if (tid < Hz) tv = make_float2(t0[tid], t1[tid]);
    __syncthreads();

    for (int t = 0; t < Tz; t++) {
        float2 tn = make_float2(0.f, 0.f);
        float2 m2 = make_float2(0.f, 0.f);
        if (tid < Hz) {
            if (t + 1 < Tz)
                tn = make_float2(t0[(size_t)(t + 1) * Hz + tid],
                                 t1[(size_t)(t + 1) * Hz + tid]);
            #pragma unroll
            for (int k = 0; k < Hz; k++) {
                float2 s = st[k];
                m2.x += w[k] * s.x;
                m2.y += w[k] * s.y;
            }
            float2 s = st[tid];
            pg[tid] = make_float2(wl * s.x, wl * s.y);
        } else if (tid < 104) {
            int which = tid - Hz;   // 0..3
            if (which == 0) aux[0] = g_li[(size_t)b0 * Tz + t];
            if (which == 1) aux[1] = g_li[(size_t)b1 * Tz + t];
            if (which == 2) aux[2] = g_z[(size_t)b0 * Tz + t];
            if (which == 3) aux[3] = g_z[(size_t)b1 * Tz + t];
        }
        __syncthreads();
        if (tid < 32) {
            float ax = 0.f, ay = 0.f;
            for (int k = tid; k < Hz; k += 32) {
                ax += pg[k].x;
                ay += pg[k].y;
            }
            #pragma unroll
            for (int o = 16; o > 0; o >>= 1) {
                ax += __shfl_xor_sync(0xffffffffu, ax, o);
                ay += __shfl_xor_sync(0xffffffffu, ay, o);
            }
            if (tid == 0)
                gsh = make_float2(sigf(aux[0] + ax + bl), sigf(aux[1] + ay + bl));
        }
        __syncthreads();
        if (tid < Hz) {
            float2 gv = gsh;
            float nsx = tanh_fast(tv.x + gv.x * m2.x + bt);
            float nsy = tanh_fast(tv.y + gv.y * m2.y + bt);
            float zx = aux[2], zy = aux[3];
            float2 s = st[tid];
            st[tid] = make_float2((1.f - zx) * s.x + zx * nsx,
                                  (1.f - zy) * s.y + zy * nsy);
            tv = tn;
        }
        __syncthreads();
    }
    if (tid < Hz) {
        g_state[b0 * Hz + tid] = st[tid].x;
        g_state[b1 * Hz + tid] = st[tid].y;
    }
}

// ---------------- K7: output projection ----------------
__global__ void __launch_bounds__(256) out_kernel(const float* __restrict__ Wout,
                                                  const float* __restrict__ bout,
                                                  float* __restrict__ out) {
    int idx = blockIdx.x * 256 + threadIdx.x;
    if (idx >= Bz * NCz) return;
    int b = idx / NCz, c = idx % NCz;
    float acc = bout[c];
    const float* s = g_state + b * Hz;
    const float* wr = Wout + c * Hz;
    #pragma unroll
    for (int k = 0; k < Hz; k++) acc += s[k] * wr[k];
    out[idx] = acc;
}

// ---------------- launch ----------------
extern "C" void kernel_launch(void* const* d_in, const int* in_sizes, int n_in,
                              void* d_out, int out_size) {
    const int*   txt   = (const int*)d_in[0];
    const int*   lens  = (const int*)d_in[1];
    const float* emb   = (const float*)d_in[2];
    const float* W_ih  = (const float*)d_in[3];
    const float* W_hh  = (const float*)d_in[4];
    const float* b_ih  = (const float*)d_in[5];
    const float* b_hh  = (const float*)d_in[6];
    const float* W_lgr = (const float*)d_in[7];
    const float* b_lgr = (const float*)d_in[8];
    const float* W_ts  = (const float*)d_in[9];
    const float* b_ts  = (const float*)d_in[10];
    const float* W_ti  = (const float*)d_in[11];
    const float* b_ti  = (const float*)d_in[12];
    const float* W_out = (const float*)d_in[13];
    const float* b_out = (const float*)d_in[14];
    float* out = (float*)d_out;

    float* xp  = nullptr; cudaGetSymbolAddress((void**)&xp,  g_xp);
    float* rnn = nullptr; cudaGetSymbolAddress((void**)&rnn, g_rnn);
    float* ti  = nullptr; cudaGetSymbolAddress((void**)&ti,  g_ti);

    // K1: embedding-row norm scales
    scale_kernel<<<BT / 8, 256>>>(txt, emb);

    // K2: xp = norm(emb[txt]) @ W_ih^T + b_ih   (tf32 MMA)
    {
        constexpr int SMEM = (64 + 160) * 204 * 4;   // 182784 B
        cudaFuncSetAttribute((const void*)mma_gemm_kernel<200, 200, 204, 160, 40, true>,
                             cudaFuncAttributeMaxDynamicSharedMemorySize, SMEM);
        dim3 grid(BT / 64, 2);
        mma_gemm_kernel<200, 200, 204, 160, 40, true><<<grid, 256, SMEM>>>(
            nullptr, txt, emb, W_ih, b_ih, xp, 300);
    }

    // K3: GRU scan
    gru_kernel<<<Bz / 2, 320>>>(W_hh, b_hh);

    // K4: z (attention gate) and lgr_in
    zli_kernel<<<BT / 8, 256>>>(W_lgr, lens);

    // K5: ti = rnn @ W_ti^T + b_ti   (tf32 MMA)
    {
        constexpr int SMEM = (64 + 128) * 108 * 4;   // 82944 B
        cudaFuncSetAttribute((const void*)mma_gemm_kernel<100, 104, 108, 128, 32, false>,
                             cudaFuncAttributeMaxDynamicSharedMemorySize, SMEM);
        dim3 grid(BT / 64, 1);
        mma_gemm_kernel<100, 104, 108, 128, 32, false><<<grid, 256, SMEM>>>(
            rnn, nullptr, nullptr, W_ti, b_ti, ti, 100);
    }

    // K6: second recurrence
    rec_kernel<<<Bz / 2, 128>>>(W_ts, b_ts, W_lgr, b_lgr);

    // K7: output projection
    out_kernel<<<(Bz * NCz + 255) / 256, 256>>>(W_out, b_out, out);
}